// round 10
// baseline (speedup 1.0000x reference)
#include <cuda_runtime.h>
#include <cstdint>
#include <cstddef>

// Problem: B=64, T=2048, D=512, H=512
#define NCTA 128
#define NTHR 256
#define HP   516   // padded SMEM row stride (516 % 32 == 4 -> conflict-free)

// ---------------- static device scratch (no runtime allocation) ----------------
__device__ float g_xzr[64ull * 2048 * 1024];  // [B,T,2H] input zr projection
__device__ float g_xo [64ull * 2048 * 512];   // [B,T,H]  input o  projection
__device__ float g_h  [64 * 512];             // current hidden state
__device__ float g_rg [64 * 512];             // h * sigmoid(r)
__device__ int          g_cnt   = 0;
__device__ volatile int g_sense = 0;

// ---------------------------------------------------------------------------
// Kernel 1: fused input-projection SGEMM
//   n in [0,1024):    g_xzr[m,n] = seq[m,:] . W_i2h[n,:] + b_i2h[n]
//   n in [1024,1536): g_xo [m,n-1024] likewise with W_i2o/b_i2o
// Tiles BM=128, BN=64, BK=16; 256 threads; 8x4 micro-tile; reg prefetch.
// ---------------------------------------------------------------------------
__global__ __launch_bounds__(256) void proj_gemm(
    const float* __restrict__ A,
    const float* __restrict__ Wih, const float* __restrict__ bih,
    const float* __restrict__ Wio, const float* __restrict__ bio)
{
    __shared__ __align__(16) float As[16][132];  // [k][m]
    __shared__ __align__(16) float Bs[16][68];   // [k][n]

    const int tid = threadIdx.x;
    const int n0  = blockIdx.x * 64;
    const size_t m0 = (size_t)blockIdx.y * 128;

    const float* W; const float* bias; float* out; int ldo; int nc0;
    if (n0 < 1024) { W = Wih; bias = bih; out = g_xzr; ldo = 1024; nc0 = n0; }
    else           { W = Wio; bias = bio; out = g_xo;  ldo = 512;  nc0 = n0 - 1024; }

    const int ar  = tid >> 2;   // 0..63 staging row
    const int ac4 = tid & 3;    // float4 slot along K
    const int ty  = tid >> 4;   // 0..15 -> 8 M rows each
    const int tx  = tid & 15;   // 0..15 -> 4 N cols each

    float acc[8][4];
#pragma unroll
    for (int i = 0; i < 8; i++)
#pragma unroll
        for (int j = 0; j < 4; j++) acc[i][j] = 0.f;

    float4 pa0 = *(const float4*)(A + (m0 + ar) * 512 + ac4 * 4);
    float4 pa1 = *(const float4*)(A + (m0 + 64 + ar) * 512 + ac4 * 4);
    float4 pb  = *(const float4*)(W + (size_t)(nc0 + ar) * 512 + ac4 * 4);

    for (int k0 = 0; k0 < 512; k0 += 16) {
        As[ac4*4+0][ar]      = pa0.x; As[ac4*4+1][ar]      = pa0.y;
        As[ac4*4+2][ar]      = pa0.z; As[ac4*4+3][ar]      = pa0.w;
        As[ac4*4+0][64 + ar] = pa1.x; As[ac4*4+1][64 + ar] = pa1.y;
        As[ac4*4+2][64 + ar] = pa1.z; As[ac4*4+3][64 + ar] = pa1.w;
        Bs[ac4*4+0][ar] = pb.x; Bs[ac4*4+1][ar] = pb.y;
        Bs[ac4*4+2][ar] = pb.z; Bs[ac4*4+3][ar] = pb.w;
        __syncthreads();

        if (k0 + 16 < 512) {
            pa0 = *(const float4*)(A + (m0 + ar) * 512 + k0 + 16 + ac4 * 4);
            pa1 = *(const float4*)(A + (m0 + 64 + ar) * 512 + k0 + 16 + ac4 * 4);
            pb  = *(const float4*)(W + (size_t)(nc0 + ar) * 512 + k0 + 16 + ac4 * 4);
        }

#pragma unroll
        for (int kk = 0; kk < 16; kk++) {
            float4 a0 = *(const float4*)&As[kk][ty * 8];
            float4 a1 = *(const float4*)&As[kk][ty * 8 + 4];
            float4 bv = *(const float4*)&Bs[kk][tx * 4];
            float av[8] = {a0.x, a0.y, a0.z, a0.w, a1.x, a1.y, a1.z, a1.w};
#pragma unroll
            for (int i = 0; i < 8; i++) {
                acc[i][0] += av[i] * bv.x;
                acc[i][1] += av[i] * bv.y;
                acc[i][2] += av[i] * bv.z;
                acc[i][3] += av[i] * bv.w;
            }
        }
        __syncthreads();
    }

    float4 bv4 = *(const float4*)(bias + nc0 + tx * 4);
#pragma unroll
    for (int i = 0; i < 8; i++) {
        float4 v;
        v.x = acc[i][0] + bv4.x; v.y = acc[i][1] + bv4.y;
        v.z = acc[i][2] + bv4.z; v.w = acc[i][3] + bv4.w;
        *(float4*)(out + (m0 + ty * 8 + i) * ldo + nc0 + tx * 4) = v;
    }
}

// ---------------------------------------------------------------------------
// Persistent recurrence kernel
// ---------------------------------------------------------------------------
__device__ __forceinline__ void stcg(float* p, float v) {
    asm volatile("st.global.cg.f32 [%0], %1;" :: "l"(p), "f"(v));
}

// copy 64x256 fp32 block (cols [kbase,kbase+256)) of src[64][512] into
// dst[64][HP] via cp.async.cg (L2 path -> cross-CTA coherent)
__device__ __forceinline__ void stage(const float* __restrict__ src,
                                      float* dst, int kbase)
{
    const int t = threadIdx.x;
#pragma unroll
    for (int i = 0; i < 16; i++) {
        int idx = t + i * NTHR;       // 0..4095 float4 units
        int bb  = idx >> 6;           // batch row
        int kq  = idx & 63;           // float4 within chunk
        const float* s = src + bb * 512 + kbase + kq * 4;
        float*       d = dst + bb * HP + kbase + kq * 4;
        unsigned sa = (unsigned)__cvta_generic_to_shared(d);
        asm volatile("cp.async.cg.shared.global [%0], [%1], 16;"
                     :: "r"(sa), "l"(s));
    }
}

// sense-reversal grid barrier (all NCTA CTAs co-resident)
__device__ __forceinline__ void gbar(int* ls) {
    __threadfence();
    __syncthreads();
    if (threadIdx.x == 0) {
        int s = *ls ^ 1; *ls = s;
        if (atomicAdd(&g_cnt, 1) == NCTA - 1) {
            g_cnt = 0;
            __threadfence();
            g_sense = s;
        } else {
            while (g_sense != s) __nanosleep(32);
        }
        __threadfence();
    }
    __syncthreads();
}

__global__ __launch_bounds__(NTHR, 1) void gru_rec(
    const int*   __restrict__ lens,
    const float* __restrict__ Whh, const float* __restrict__ bhh,
    const float* __restrict__ Who, const float* __restrict__ bho,
    float* __restrict__ out)
{
    extern __shared__ float sm[];
    float* Wz = sm;             // [4][HP]
    float* Wr = sm + 4 * HP;    // [4][HP]
    float* Wo = sm + 8 * HP;    // [4][HP]
    float* hb = sm + 12 * HP;   // [64][HP]  (h or rg staging)
    __shared__ int ls;

    const int tid = threadIdx.x;
    const int b   = tid >> 2;         // batch row this thread owns
    const int j   = tid & 3;          // local column
    const int jg  = blockIdx.x * 4 + j;

    if (tid == 0) ls = g_sense;       // replay-safe barrier sense init

    // stage weight slices once (reused for all 2048 steps)
    for (int idx = tid; idx < 4 * 512; idx += NTHR) {
        int jj = idx >> 9, k = idx & 511;
        int row = blockIdx.x * 4 + jj;
        Wz[jj * HP + k] = Whh[(size_t)row * 512 + k];
        Wr[jj * HP + k] = Whh[(size_t)(512 + row) * 512 + k];
        Wo[jj * HP + k] = Who[(size_t)row * 512 + k];
    }

    const float bz = bhh[jg], br = bhh[512 + jg], bo = bho[jg];
    const int   lb = lens[b];
    float myh = 0.f;
    stcg(&g_h[b * 512 + jg], 0.f);    // h0 = 0 (must reset every replay)
    __syncthreads();
    gbar(&ls);                        // all CTAs see zeroed h

    float* outF = out + 64ull * 2048 * 512;   // final_state region

    for (int t = 0; t < 2048; t++) {
        // ---------- phase A: z/r preacts, publish rg = h * sigmoid(r) ----------
        stage(g_h, hb, 0);   asm volatile("cp.async.commit_group;");
        stage(g_h, hb, 256); asm volatile("cp.async.commit_group;");

        const size_t rowzr = ((size_t)b * 2048 + t) * 1024;
        float az = bz + g_xzr[rowzr + jg];
        float ar = br + g_xzr[rowzr + 512 + jg];

        asm volatile("cp.async.wait_group 1;");
        __syncthreads();
        {
            const float4* hv = (const float4*)(hb + b * HP);
            const float4* wz = (const float4*)(Wz + j * HP);
            const float4* wr = (const float4*)(Wr + j * HP);
#pragma unroll 8
            for (int q = 0; q < 64; q++) {
                float4 h4 = hv[q], z4 = wz[q], r4 = wr[q];
                az += h4.x*z4.x + h4.y*z4.y + h4.z*z4.z + h4.w*z4.w;
                ar += h4.x*r4.x + h4.y*r4.y + h4.z*r4.z + h4.w*r4.w;
            }
            asm volatile("cp.async.wait_group 0;");
            __syncthreads();
#pragma unroll 8
            for (int q = 64; q < 128; q++) {
                float4 h4 = hv[q], z4 = wz[q], r4 = wr[q];
                az += h4.x*z4.x + h4.y*z4.y + h4.z*z4.z + h4.w*z4.w;
                ar += h4.x*r4.x + h4.y*r4.y + h4.z*r4.z + h4.w*r4.w;
            }
        }
        float sr = 1.f / (1.f + expf(-ar));
        stcg(&g_rg[b * 512 + jg], myh * sr);
        float zs = 1.f / (1.f + expf(-az));
        gbar(&ls);

        // ---------- phase B: s preact, state update ----------
        stage(g_rg, hb, 0);   asm volatile("cp.async.commit_group;");
        stage(g_rg, hb, 256); asm volatile("cp.async.commit_group;");

        float as_ = bo + g_xo[((size_t)b * 2048 + t) * 512 + jg];

        asm volatile("cp.async.wait_group 1;");
        __syncthreads();
        {
            const float4* rv = (const float4*)(hb + b * HP);
            const float4* wo = (const float4*)(Wo + j * HP);
#pragma unroll 8
            for (int q = 0; q < 64; q++) {
                float4 h4 = rv[q], o4 = wo[q];
                as_ += h4.x*o4.x + h4.y*o4.y + h4.z*o4.z + h4.w*o4.w;
            }
            asm volatile("cp.async.wait_group 0;");
            __syncthreads();
#pragma unroll 8
            for (int q = 64; q < 128; q++) {
                float4 h4 = rv[q], o4 = wo[q];
                as_ += h4.x*o4.x + h4.y*o4.y + h4.z*o4.z + h4.w*o4.w;
            }
        }
        float hn  = (1.f - zs) * myh + zs * tanhf(as_);
        bool  act = (t < lb);
        out[((size_t)b * 2048 + t) * 512 + jg] = act ? hn : 0.f;
        if (act) myh = hn;
        stcg(&g_h[b * 512 + jg], myh);
        gbar(&ls);
    }

    outF[b * 512 + jg] = myh;   // final_state (1,B,H)
}

// ---------------------------------------------------------------------------
extern "C" void kernel_launch(void* const* d_in, const int* in_sizes, int n_in,
                              void* d_out, int out_size)
{
    const float* seq  = (const float*)d_in[0];
    const int*   lens = (const int*)  d_in[1];
    const float* Wih  = (const float*)d_in[2];
    const float* bih  = (const float*)d_in[3];
    const float* Whh  = (const float*)d_in[4];
    const float* bhh  = (const float*)d_in[5];
    const float* Wio  = (const float*)d_in[6];
    const float* bio  = (const float*)d_in[7];
    const float* Who  = (const float*)d_in[8];
    const float* bho  = (const float*)d_in[9];
    float* out = (float*)d_out;

    const int smem = (12 * HP + 64 * HP) * (int)sizeof(float);  // 156,864 B
    cudaFuncSetAttribute(gru_rec, cudaFuncAttributeMaxDynamicSharedMemorySize,
                         smem);

    dim3 grid(24, 1024);   // N tiles (16 zr + 8 o) x M tiles
    proj_gemm<<<grid, 256>>>(seq, Wih, bih, Wio, bio);
    gru_rec<<<NCTA, NTHR, smem>>>(lens, Whh, bhh, Who, bho, out);
}

// round 11
// speedup vs baseline: 1.0788x; 1.0788x over previous
#include <cuda_runtime.h>
#include <cstdint>
#include <cstddef>

// Problem: B=64, T=2048, D=512, H=512
#define NCTA 128      // 16 column-groups x 8 batch-groups
#define NTHR 256
#define WPAD 516      // padded SMEM row stride (516 % 32 == 4 -> conflict-free)

// ---------------- static device scratch (no runtime allocation) ----------------
__device__ float g_xzr[64ull * 2048 * 1024];  // [B,T,2H] input zr projection
__device__ float g_xo [64ull * 2048 * 512];   // [B,T,H]  input o  projection
__device__ float g_h  [64 * 512];             // current hidden state
__device__ float g_rg [64 * 512];             // h * sigmoid(r)
__device__ int          g_cnt   = 0;
__device__ volatile int g_sense = 0;

// ---------------- f32x2 packed-FMA helpers (PTX-only on sm_103a) ----------------
__device__ __forceinline__ void fma2(unsigned long long& d,
                                     unsigned long long a, unsigned long long b) {
    asm("fma.rn.f32x2 %0, %1, %2, %0;" : "+l"(d) : "l"(a), "l"(b));
}
__device__ __forceinline__ unsigned long long pk(float lo, float hi) {
    unsigned long long r;
    asm("mov.b64 %0, {%1, %2};" : "=l"(r) : "f"(lo), "f"(hi));
    return r;
}
__device__ __forceinline__ float2 upk(unsigned long long v) {
    float2 f;
    asm("mov.b64 {%0, %1}, %2;" : "=f"(f.x), "=f"(f.y) : "l"(v));
    return f;
}

// ---------------------------------------------------------------------------
// Kernel 1: fused input-projection SGEMM (f32x2 packed over k-pairs)
//   n in [0,1024):    g_xzr[m,n] = seq[m,:] . W_i2h[n,:] + b_i2h[n]
//   n in [1024,1536): g_xo [m,n-1024] likewise with W_i2o/b_i2o
// Tiles BM=128, BN=64, BK=16; 256 threads; 8x4 micro-tile; reg prefetch.
// ---------------------------------------------------------------------------
__global__ __launch_bounds__(256) void proj_gemm(
    const float* __restrict__ A,
    const float* __restrict__ Wih, const float* __restrict__ bih,
    const float* __restrict__ Wio, const float* __restrict__ bio)
{
    __shared__ __align__(16) float As[16][132];  // [k][m]
    __shared__ __align__(16) float Bs[16][68];   // [k][n]

    const int tid = threadIdx.x;
    const int n0  = blockIdx.x * 64;
    const size_t m0 = (size_t)blockIdx.y * 128;

    const float* W; const float* bias; float* out; int ldo; int nc0;
    if (n0 < 1024) { W = Wih; bias = bih; out = g_xzr; ldo = 1024; nc0 = n0; }
    else           { W = Wio; bias = bio; out = g_xo;  ldo = 512;  nc0 = n0 - 1024; }

    const int ar  = tid >> 2;   // 0..63 staging row
    const int ac4 = tid & 3;    // float4 slot along K
    const int ty  = tid >> 4;   // 0..15 -> 8 M rows each
    const int tx  = tid & 15;   // 0..15 -> 4 N cols each

    unsigned long long acc[8][4];   // packed k-even/k-odd partial sums
#pragma unroll
    for (int i = 0; i < 8; i++)
#pragma unroll
        for (int j = 0; j < 4; j++) acc[i][j] = 0ull;

    float4 pa0 = *(const float4*)(A + (m0 + ar) * 512 + ac4 * 4);
    float4 pa1 = *(const float4*)(A + (m0 + 64 + ar) * 512 + ac4 * 4);
    float4 pb  = *(const float4*)(W + (size_t)(nc0 + ar) * 512 + ac4 * 4);

    for (int k0 = 0; k0 < 512; k0 += 16) {
        As[ac4*4+0][ar]      = pa0.x; As[ac4*4+1][ar]      = pa0.y;
        As[ac4*4+2][ar]      = pa0.z; As[ac4*4+3][ar]      = pa0.w;
        As[ac4*4+0][64 + ar] = pa1.x; As[ac4*4+1][64 + ar] = pa1.y;
        As[ac4*4+2][64 + ar] = pa1.z; As[ac4*4+3][64 + ar] = pa1.w;
        Bs[ac4*4+0][ar] = pb.x; Bs[ac4*4+1][ar] = pb.y;
        Bs[ac4*4+2][ar] = pb.z; Bs[ac4*4+3][ar] = pb.w;
        __syncthreads();

        if (k0 + 16 < 512) {
            pa0 = *(const float4*)(A + (m0 + ar) * 512 + k0 + 16 + ac4 * 4);
            pa1 = *(const float4*)(A + (m0 + 64 + ar) * 512 + k0 + 16 + ac4 * 4);
            pb  = *(const float4*)(W + (size_t)(nc0 + ar) * 512 + k0 + 16 + ac4 * 4);
        }

#pragma unroll
        for (int kp = 0; kp < 8; kp++) {
            const int kk = kp * 2;
            float4 al0 = *(const float4*)&As[kk][ty * 8];
            float4 al1 = *(const float4*)&As[kk][ty * 8 + 4];
            float4 ah0 = *(const float4*)&As[kk + 1][ty * 8];
            float4 ah1 = *(const float4*)&As[kk + 1][ty * 8 + 4];
            float4 bl  = *(const float4*)&Bs[kk][tx * 4];
            float4 bh  = *(const float4*)&Bs[kk + 1][tx * 4];
            unsigned long long pbv[4] = {
                pk(bl.x, bh.x), pk(bl.y, bh.y), pk(bl.z, bh.z), pk(bl.w, bh.w) };
            float alv[8] = {al0.x, al0.y, al0.z, al0.w, al1.x, al1.y, al1.z, al1.w};
            float ahv[8] = {ah0.x, ah0.y, ah0.z, ah0.w, ah1.x, ah1.y, ah1.z, ah1.w};
#pragma unroll
            for (int i = 0; i < 8; i++) {
                unsigned long long pav = pk(alv[i], ahv[i]);
                fma2(acc[i][0], pav, pbv[0]);
                fma2(acc[i][1], pav, pbv[1]);
                fma2(acc[i][2], pav, pbv[2]);
                fma2(acc[i][3], pav, pbv[3]);
            }
        }
        __syncthreads();
    }

    float4 bv4 = *(const float4*)(bias + nc0 + tx * 4);
#pragma unroll
    for (int i = 0; i < 8; i++) {
        float2 c0 = upk(acc[i][0]), c1 = upk(acc[i][1]);
        float2 c2 = upk(acc[i][2]), c3 = upk(acc[i][3]);
        float4 v;
        v.x = c0.x + c0.y + bv4.x; v.y = c1.x + c1.y + bv4.y;
        v.z = c2.x + c2.y + bv4.z; v.w = c3.x + c3.y + bv4.w;
        *(float4*)(out + (m0 + ty * 8 + i) * ldo + nc0 + tx * 4) = v;
    }
}

// ---------------------------------------------------------------------------
// Persistent recurrence kernel: 128 CTAs = 16 col-groups x 8 batch-groups.
// CTA owns 8 batch rows x 32 hidden columns; weight slices resident in SMEM.
// ---------------------------------------------------------------------------
__device__ __forceinline__ void stcg(float* p, float v) {
    asm volatile("st.global.cg.f32 [%0], %1;" :: "l"(p), "f"(v));
}

// stage rows [b0, b0+8), cols [kbase, kbase+256) of src[64][512] -> dst[8][WPAD]
// cp.async.cg: L2 path -> coherent with other CTAs' st.global.cg
__device__ __forceinline__ void stage8(const float* __restrict__ src,
                                       float* dst, int b0, int kbase)
{
    const int t = threadIdx.x;
#pragma unroll
    for (int i = 0; i < 2; i++) {
        int idx = t + i * NTHR;      // 0..511 float4 units
        int r   = idx >> 6;          // local batch row 0..7
        int q   = idx & 63;          // float4 within 256-col chunk
        const float* s = src + (size_t)(b0 + r) * 512 + kbase + q * 4;
        float*       d = dst + r * WPAD + kbase + q * 4;
        unsigned sa = (unsigned)__cvta_generic_to_shared(d);
        asm volatile("cp.async.cg.shared.global [%0], [%1], 16;"
                     :: "r"(sa), "l"(s));
    }
}

// sense-reversal grid barrier (all NCTA CTAs co-resident)
__device__ __forceinline__ void gbar(int* ls) {
    __threadfence();
    __syncthreads();
    if (threadIdx.x == 0) {
        int s = *ls ^ 1; *ls = s;
        if (atomicAdd(&g_cnt, 1) == NCTA - 1) {
            g_cnt = 0;
            __threadfence();
            g_sense = s;
        } else {
            while (g_sense != s) __nanosleep(16);
        }
        __threadfence();
    }
    __syncthreads();
}

__global__ __launch_bounds__(NTHR, 1) void gru_rec(
    const int*   __restrict__ lens,
    const float* __restrict__ Whh, const float* __restrict__ bhh,
    const float* __restrict__ Who, const float* __restrict__ bho,
    float* __restrict__ out)
{
    extern __shared__ float sm[];
    float* Wz = sm;                  // [32][WPAD]
    float* Wr = sm + 32 * WPAD;      // [32][WPAD]
    float* Wo = sm + 64 * WPAD;      // [32][WPAD]
    float* hb = sm + 96 * WPAD;      // [8][WPAD] staging (h or rg)
    __shared__ int ls;

    const int tid  = threadIdx.x;
    const int w    = tid >> 5;
    const int lane = tid & 31;
    const int cg   = blockIdx.x >> 3;      // 0..15 column group
    const int bg   = blockIdx.x & 7;       // 0..7  batch group
    const int j_local = w * 4 + (lane & 3);
    const int b_local = lane >> 2;
    const int jg = cg * 32 + j_local;
    const int b0 = bg * 8;
    const int b  = b0 + b_local;

    if (tid == 0) ls = g_sense;            // replay-safe sense init

    // stage weight slices once (reused across all 2048 steps)
    for (int idx = tid; idx < 32 * 128; idx += NTHR) {
        int jj = idx >> 7, q = idx & 127;
        *(float4*)&Wz[jj * WPAD + q * 4] =
            *(const float4*)&Whh[(size_t)(cg * 32 + jj) * 512 + q * 4];
        *(float4*)&Wr[jj * WPAD + q * 4] =
            *(const float4*)&Whh[(size_t)(512 + cg * 32 + jj) * 512 + q * 4];
        *(float4*)&Wo[jj * WPAD + q * 4] =
            *(const float4*)&Who[(size_t)(cg * 32 + jj) * 512 + q * 4];
    }

    const float bz = bhh[jg], br = bhh[512 + jg], bo = bho[jg];
    const int   lb = lens[b];
    float myh = 0.f;
    stcg(&g_h[b * 512 + jg], 0.f);         // h0 = 0 every launch/replay
    __syncthreads();
    gbar(&ls);                             // all CTAs see zeroed h + weights staged

    float* outF = out + 64ull * 2048 * 512;   // final_state region

    const ulonglong2* zv = (const ulonglong2*)(Wz + j_local * WPAD);
    const ulonglong2* rv = (const ulonglong2*)(Wr + j_local * WPAD);
    const ulonglong2* ov = (const ulonglong2*)(Wo + j_local * WPAD);
    const ulonglong2* hv = (const ulonglong2*)(hb + b_local * WPAD);

    for (int t = 0; t < 2048; t++) {
        // ---------- phase A: z/r preacts, publish rg = h * sigmoid(r) ----------
        stage8(g_h, hb, b0, 0);   asm volatile("cp.async.commit_group;");
        stage8(g_h, hb, b0, 256); asm volatile("cp.async.commit_group;");

        const size_t rowzr = ((size_t)b * 2048 + t) * 1024;
        const float xz = g_xzr[rowzr + jg];
        const float xr = g_xzr[rowzr + 512 + jg];

        unsigned long long az0 = 0, az1 = 0, ar0 = 0, ar1 = 0;

        asm volatile("cp.async.wait_group 1;");
        __syncthreads();
#pragma unroll 8
        for (int q = 0; q < 64; q++) {
            ulonglong2 h2 = hv[q], z2 = zv[q], r2 = rv[q];
            fma2(az0, h2.x, z2.x); fma2(az1, h2.y, z2.y);
            fma2(ar0, h2.x, r2.x); fma2(ar1, h2.y, r2.y);
        }
        asm volatile("cp.async.wait_group 0;");
        __syncthreads();
#pragma unroll 8
        for (int q = 64; q < 128; q++) {
            ulonglong2 h2 = hv[q], z2 = zv[q], r2 = rv[q];
            fma2(az0, h2.x, z2.x); fma2(az1, h2.y, z2.y);
            fma2(ar0, h2.x, r2.x); fma2(ar1, h2.y, r2.y);
        }
        float2 z0 = upk(az0), z1 = upk(az1), r0 = upk(ar0), r1 = upk(ar1);
        float az = bz + xz + z0.x + z0.y + z1.x + z1.y;
        float ar = br + xr + r0.x + r0.y + r1.x + r1.y;
        float sr = 1.f / (1.f + expf(-ar));
        stcg(&g_rg[b * 512 + jg], myh * sr);
        float zs = 1.f / (1.f + expf(-az));
        gbar(&ls);

        // ---------- phase B: s preact, state update ----------
        stage8(g_rg, hb, b0, 0);   asm volatile("cp.async.commit_group;");
        stage8(g_rg, hb, b0, 256); asm volatile("cp.async.commit_group;");

        const float xo = g_xo[((size_t)b * 2048 + t) * 512 + jg];
        unsigned long long ao0 = 0, ao1 = 0;

        asm volatile("cp.async.wait_group 1;");
        __syncthreads();
#pragma unroll 8
        for (int q = 0; q < 64; q++) {
            ulonglong2 h2 = hv[q], o2 = ov[q];
            fma2(ao0, h2.x, o2.x); fma2(ao1, h2.y, o2.y);
        }
        asm volatile("cp.async.wait_group 0;");
        __syncthreads();
#pragma unroll 8
        for (int q = 64; q < 128; q++) {
            ulonglong2 h2 = hv[q], o2 = ov[q];
            fma2(ao0, h2.x, o2.x); fma2(ao1, h2.y, o2.y);
        }
        float2 o0 = upk(ao0), o1 = upk(ao1);
        float as_ = bo + xo + o0.x + o0.y + o1.x + o1.y;

        float hn  = (1.f - zs) * myh + zs * tanhf(as_);
        bool  act = (t < lb);
        out[((size_t)b * 2048 + t) * 512 + jg] = act ? hn : 0.f;
        if (act) myh = hn;
        stcg(&g_h[b * 512 + jg], myh);
        gbar(&ls);
    }

    outF[b * 512 + jg] = myh;   // final_state (1,B,H)
}

// ---------------------------------------------------------------------------
extern "C" void kernel_launch(void* const* d_in, const int* in_sizes, int n_in,
                              void* d_out, int out_size)
{
    const float* seq  = (const float*)d_in[0];
    const int*   lens = (const int*)  d_in[1];
    const float* Wih  = (const float*)d_in[2];
    const float* bih  = (const float*)d_in[3];
    const float* Whh  = (const float*)d_in[4];
    const float* bhh  = (const float*)d_in[5];
    const float* Wio  = (const float*)d_in[6];
    const float* bio  = (const float*)d_in[7];
    const float* Who  = (const float*)d_in[8];
    const float* bho  = (const float*)d_in[9];
    float* out = (float*)d_out;

    const int smem = (96 * WPAD + 8 * WPAD) * (int)sizeof(float);  // 214,656 B
    cudaFuncSetAttribute(gru_rec, cudaFuncAttributeMaxDynamicSharedMemorySize,
                         smem);

    dim3 grid(24, 1024);   // N tiles (16 zr + 8 o) x M tiles
    proj_gemm<<<grid, 256>>>(seq, Wih, bih, Wio, bio);
    gru_rec<<<NCTA, NTHR, smem>>>(lens, Whh, bhh, Who, bho, out);
}

// round 12
// speedup vs baseline: 1.1565x; 1.0720x over previous
#include <cuda_runtime.h>
#include <cstdint>
#include <cstddef>

// Problem: B=64, T=2048, D=512, H=512
#define NCTA 128      // 16 column-groups x 8 batch-groups
#define NTHR 256
#define WPAD 516      // padded SMEM row stride (516 % 32 == 4 -> conflict-free)

// ---------------- static device scratch (no runtime allocation) ----------------
__device__ float g_xzr[64ull * 2048 * 1024];  // [B,T,2H] input zr projection
__device__ float g_xo [64ull * 2048 * 512];   // [B,T,H]  input o  projection
__device__ float g_h  [64 * 512];             // current hidden state
__device__ float g_rg [64 * 512];             // h * sigmoid(r)
__device__ int   g_cnt   = 0;
__device__ int   g_sense = 0;

// ---------------- f32x2 packed-FMA helpers (PTX-only on sm_103a) ----------------
__device__ __forceinline__ void fma2(unsigned long long& d,
                                     unsigned long long a, unsigned long long b) {
    asm("fma.rn.f32x2 %0, %1, %2, %0;" : "+l"(d) : "l"(a), "l"(b));
}
__device__ __forceinline__ unsigned long long pk(float lo, float hi) {
    unsigned long long r;
    asm("mov.b64 %0, {%1, %2};" : "=l"(r) : "f"(lo), "f"(hi));
    return r;
}
__device__ __forceinline__ float2 upk(unsigned long long v) {
    float2 f;
    asm("mov.b64 {%0, %1}, %2;" : "=f"(f.x), "=f"(f.y) : "l"(v));
    return f;
}

// ---------------------------------------------------------------------------
// Kernel 1: fused input-projection SGEMM (f32x2 packed over k-pairs)
//   n in [0,1024):    g_xzr[m,n] = seq[m,:] . W_i2h[n,:] + b_i2h[n]
//   n in [1024,1536): g_xo [m,n-1024] likewise with W_i2o/b_i2o
// ---------------------------------------------------------------------------
__global__ __launch_bounds__(256) void proj_gemm(
    const float* __restrict__ A,
    const float* __restrict__ Wih, const float* __restrict__ bih,
    const float* __restrict__ Wio, const float* __restrict__ bio)
{
    __shared__ __align__(16) float As[16][132];  // [k][m]
    __shared__ __align__(16) float Bs[16][68];   // [k][n]

    const int tid = threadIdx.x;
    const int n0  = blockIdx.x * 64;
    const size_t m0 = (size_t)blockIdx.y * 128;

    const float* W; const float* bias; float* out; int ldo; int nc0;
    if (n0 < 1024) { W = Wih; bias = bih; out = g_xzr; ldo = 1024; nc0 = n0; }
    else           { W = Wio; bias = bio; out = g_xo;  ldo = 512;  nc0 = n0 - 1024; }

    const int ar  = tid >> 2;
    const int ac4 = tid & 3;
    const int ty  = tid >> 4;
    const int tx  = tid & 15;

    unsigned long long acc[8][4];
#pragma unroll
    for (int i = 0; i < 8; i++)
#pragma unroll
        for (int j = 0; j < 4; j++) acc[i][j] = 0ull;

    float4 pa0 = *(const float4*)(A + (m0 + ar) * 512 + ac4 * 4);
    float4 pa1 = *(const float4*)(A + (m0 + 64 + ar) * 512 + ac4 * 4);
    float4 pb  = *(const float4*)(W + (size_t)(nc0 + ar) * 512 + ac4 * 4);

    for (int k0 = 0; k0 < 512; k0 += 16) {
        As[ac4*4+0][ar]      = pa0.x; As[ac4*4+1][ar]      = pa0.y;
        As[ac4*4+2][ar]      = pa0.z; As[ac4*4+3][ar]      = pa0.w;
        As[ac4*4+0][64 + ar] = pa1.x; As[ac4*4+1][64 + ar] = pa1.y;
        As[ac4*4+2][64 + ar] = pa1.z; As[ac4*4+3][64 + ar] = pa1.w;
        Bs[ac4*4+0][ar] = pb.x; Bs[ac4*4+1][ar] = pb.y;
        Bs[ac4*4+2][ar] = pb.z; Bs[ac4*4+3][ar] = pb.w;
        __syncthreads();

        if (k0 + 16 < 512) {
            pa0 = *(const float4*)(A + (m0 + ar) * 512 + k0 + 16 + ac4 * 4);
            pa1 = *(const float4*)(A + (m0 + 64 + ar) * 512 + k0 + 16 + ac4 * 4);
            pb  = *(const float4*)(W + (size_t)(nc0 + ar) * 512 + k0 + 16 + ac4 * 4);
        }

#pragma unroll
        for (int kp = 0; kp < 8; kp++) {
            const int kk = kp * 2;
            float4 al0 = *(const float4*)&As[kk][ty * 8];
            float4 al1 = *(const float4*)&As[kk][ty * 8 + 4];
            float4 ah0 = *(const float4*)&As[kk + 1][ty * 8];
            float4 ah1 = *(const float4*)&As[kk + 1][ty * 8 + 4];
            float4 bl  = *(const float4*)&Bs[kk][tx * 4];
            float4 bh  = *(const float4*)&Bs[kk + 1][tx * 4];
            unsigned long long pbv[4] = {
                pk(bl.x, bh.x), pk(bl.y, bh.y), pk(bl.z, bh.z), pk(bl.w, bh.w) };
            float alv[8] = {al0.x, al0.y, al0.z, al0.w, al1.x, al1.y, al1.z, al1.w};
            float ahv[8] = {ah0.x, ah0.y, ah0.z, ah0.w, ah1.x, ah1.y, ah1.z, ah1.w};
#pragma unroll
            for (int i = 0; i < 8; i++) {
                unsigned long long pav = pk(alv[i], ahv[i]);
                fma2(acc[i][0], pav, pbv[0]);
                fma2(acc[i][1], pav, pbv[1]);
                fma2(acc[i][2], pav, pbv[2]);
                fma2(acc[i][3], pav, pbv[3]);
            }
        }
        __syncthreads();
    }

    float4 bv4 = *(const float4*)(bias + nc0 + tx * 4);
#pragma unroll
    for (int i = 0; i < 8; i++) {
        float2 c0 = upk(acc[i][0]), c1 = upk(acc[i][1]);
        float2 c2 = upk(acc[i][2]), c3 = upk(acc[i][3]);
        float4 v;
        v.x = c0.x + c0.y + bv4.x; v.y = c1.x + c1.y + bv4.y;
        v.z = c2.x + c2.y + bv4.z; v.w = c3.x + c3.y + bv4.w;
        *(float4*)(out + (m0 + ty * 8 + i) * ldo + nc0 + tx * 4) = v;
    }
}

// ---------------------------------------------------------------------------
// Persistent recurrence kernel: 128 CTAs = 16 col-groups x 8 batch-groups.
// ---------------------------------------------------------------------------

// morally-strong gpu-scope publish (no fences needed with acq/rel barrier)
__device__ __forceinline__ void st_rel(float* p, float v) {
    asm volatile("st.relaxed.gpu.global.f32 [%0], %1;" :: "l"(p), "f"(v));
}

// stage rows [b0, b0+8), cols [kbase, kbase+256) of src[64][512] -> dst[8][WPAD]
__device__ __forceinline__ void stage8(const float* __restrict__ src,
                                       float* dst, int b0, int kbase)
{
    const int t = threadIdx.x;
#pragma unroll
    for (int i = 0; i < 2; i++) {
        int idx = t + i * NTHR;
        int r   = idx >> 6;
        int q   = idx & 63;
        const float* s = src + (size_t)(b0 + r) * 512 + kbase + q * 4;
        float*       d = dst + r * WPAD + kbase + q * 4;
        unsigned sa = (unsigned)__cvta_generic_to_shared(d);
        asm volatile("cp.async.cg.shared.global [%0], [%1], 16;"
                     :: "r"(sa), "l"(s));
    }
}

// grid barrier: acq/rel atomics, single-warp tight poll, no sleeps, no membar
__device__ __forceinline__ void gbar(int& snc) {
    __syncthreads();                    // all relaxed.gpu publishes done
    snc ^= 1;
    if (threadIdx.x == 0) {
        int old;
        asm volatile("atom.acq_rel.gpu.global.add.s32 %0, [%1], 1;"
                     : "=r"(old) : "l"(&g_cnt) : "memory");
        if (old == NCTA - 1) {
            asm volatile("st.relaxed.gpu.global.s32 [%0], 0;"
                         :: "l"(&g_cnt) : "memory");
            asm volatile("st.release.gpu.global.s32 [%0], %1;"
                         :: "l"(&g_sense), "r"(snc) : "memory");
        }
    }
    if (threadIdx.x < 32) {             // warp 0 polls (one L2 stream)
        int cur;
        do {
            asm volatile("ld.acquire.gpu.global.s32 %0, [%1];"
                         : "=r"(cur) : "l"(&g_sense) : "memory");
        } while (cur != snc);
    }
    __syncthreads();
}

__global__ __launch_bounds__(NTHR, 1) void gru_rec(
    const int*   __restrict__ lens,
    const float* __restrict__ Whh, const float* __restrict__ bhh,
    const float* __restrict__ Who, const float* __restrict__ bho,
    float* __restrict__ out)
{
    extern __shared__ float sm[];
    float* Wz = sm;                  // [32][WPAD]
    float* Wr = sm + 32 * WPAD;      // [32][WPAD]
    float* Wo = sm + 64 * WPAD;      // [32][WPAD]
    float* hb = sm + 96 * WPAD;      // [8][WPAD] staging (h or rg)

    const int tid  = threadIdx.x;
    const int w    = tid >> 5;
    const int lane = tid & 31;
    const int cg   = blockIdx.x >> 3;      // 0..15 column group
    const int bg   = blockIdx.x & 7;       // 0..7  batch group
    const int j_local = w * 4 + (lane & 3);
    const int b_local = lane >> 2;
    const int jg = cg * 32 + j_local;
    const int b0 = bg * 8;
    const int b  = b0 + b_local;

    // replay-safe barrier sense init (relative to whatever value persists)
    int snc;
    asm volatile("ld.acquire.gpu.global.s32 %0, [%1];"
                 : "=r"(snc) : "l"(&g_sense) : "memory");

    // stage weight slices once (reused across all 2048 steps)
    for (int idx = tid; idx < 32 * 128; idx += NTHR) {
        int jj = idx >> 7, q = idx & 127;
        *(float4*)&Wz[jj * WPAD + q * 4] =
            *(const float4*)&Whh[(size_t)(cg * 32 + jj) * 512 + q * 4];
        *(float4*)&Wr[jj * WPAD + q * 4] =
            *(const float4*)&Whh[(size_t)(512 + cg * 32 + jj) * 512 + q * 4];
        *(float4*)&Wo[jj * WPAD + q * 4] =
            *(const float4*)&Who[(size_t)(cg * 32 + jj) * 512 + q * 4];
    }

    const float bz = bhh[jg], br = bhh[512 + jg], bo = bho[jg];
    const int   lb = lens[b];
    float myh = 0.f;
    st_rel(&g_h[b * 512 + jg], 0.f);       // h0 = 0 every launch/replay
    gbar(snc);                             // all CTAs see zeroed h

    float* outF = out + 64ull * 2048 * 512;   // final_state region

    const ulonglong2* zv = (const ulonglong2*)(Wz + j_local * WPAD);
    const ulonglong2* rv = (const ulonglong2*)(Wr + j_local * WPAD);
    const ulonglong2* ov = (const ulonglong2*)(Wo + j_local * WPAD);
    const ulonglong2* hv = (const ulonglong2*)(hb + b_local * WPAD);

    for (int t = 0; t < 2048; t++) {
        // ---------- phase A: z/r preacts, publish rg = h * sigmoid(r) ----------
        stage8(g_h, hb, b0, 0);   asm volatile("cp.async.commit_group;");
        stage8(g_h, hb, b0, 256); asm volatile("cp.async.commit_group;");

        const size_t rowzr = ((size_t)b * 2048 + t) * 1024;
        const float xz = g_xzr[rowzr + jg];
        const float xr = g_xzr[rowzr + 512 + jg];

        unsigned long long az0 = 0, az1 = 0, ar0 = 0, ar1 = 0;

        asm volatile("cp.async.wait_group 1;");
        __syncthreads();
#pragma unroll 8
        for (int q = 0; q < 64; q++) {
            ulonglong2 h2 = hv[q], z2 = zv[q], r2 = rv[q];
            fma2(az0, h2.x, z2.x); fma2(az1, h2.y, z2.y);
            fma2(ar0, h2.x, r2.x); fma2(ar1, h2.y, r2.y);
        }
        asm volatile("cp.async.wait_group 0;");
        __syncthreads();
#pragma unroll 8
        for (int q = 64; q < 128; q++) {
            ulonglong2 h2 = hv[q], z2 = zv[q], r2 = rv[q];
            fma2(az0, h2.x, z2.x); fma2(az1, h2.y, z2.y);
            fma2(ar0, h2.x, r2.x); fma2(ar1, h2.y, r2.y);
        }
        float2 z0 = upk(az0), z1 = upk(az1), r0 = upk(ar0), r1 = upk(ar1);
        float az = bz + xz + z0.x + z0.y + z1.x + z1.y;
        float ar = br + xr + r0.x + r0.y + r1.x + r1.y;
        float sr = 1.f / (1.f + expf(-ar));
        st_rel(&g_rg[b * 512 + jg], myh * sr);
        float zs = 1.f / (1.f + expf(-az));
        gbar(snc);

        // ---------- phase B: s preact, state update ----------
        stage8(g_rg, hb, b0, 0);   asm volatile("cp.async.commit_group;");
        stage8(g_rg, hb, b0, 256); asm volatile("cp.async.commit_group;");

        const float xo = g_xo[((size_t)b * 2048 + t) * 512 + jg];
        unsigned long long ao0 = 0, ao1 = 0;

        asm volatile("cp.async.wait_group 1;");
        __syncthreads();
#pragma unroll 8
        for (int q = 0; q < 64; q++) {
            ulonglong2 h2 = hv[q], o2 = ov[q];
            fma2(ao0, h2.x, o2.x); fma2(ao1, h2.y, o2.y);
        }
        asm volatile("cp.async.wait_group 0;");
        __syncthreads();
#pragma unroll 8
        for (int q = 64; q < 128; q++) {
            ulonglong2 h2 = hv[q], o2 = ov[q];
            fma2(ao0, h2.x, o2.x); fma2(ao1, h2.y, o2.y);
        }
        float2 o0 = upk(ao0), o1 = upk(ao1);
        float as_ = bo + xo + o0.x + o0.y + o1.x + o1.y;

        float hn  = (1.f - zs) * myh + zs * tanhf(as_);
        bool  act = (t < lb);
        out[((size_t)b * 2048 + t) * 512 + jg] = act ? hn : 0.f;
        if (act) myh = hn;
        st_rel(&g_h[b * 512 + jg], myh);
        gbar(snc);
    }

    outF[b * 512 + jg] = myh;   // final_state (1,B,H)
}

// ---------------------------------------------------------------------------
extern "C" void kernel_launch(void* const* d_in, const int* in_sizes, int n_in,
                              void* d_out, int out_size)
{
    const float* seq  = (const float*)d_in[0];
    const int*   lens = (const int*)  d_in[1];
    const float* Wih  = (const float*)d_in[2];
    const float* bih  = (const float*)d_in[3];
    const float* Whh  = (const float*)d_in[4];
    const float* bhh  = (const float*)d_in[5];
    const float* Wio  = (const float*)d_in[6];
    const float* bio  = (const float*)d_in[7];
    const float* Who  = (const float*)d_in[8];
    const float* bho  = (const float*)d_in[9];
    float* out = (float*)d_out;

    const int smem = (96 * WPAD + 8 * WPAD) * (int)sizeof(float);  // 214,656 B
    cudaFuncSetAttribute(gru_rec, cudaFuncAttributeMaxDynamicSharedMemorySize,
                         smem);

    dim3 grid(24, 1024);   // N tiles (16 zr + 8 o) x M tiles
    proj_gemm<<<grid, 256>>>(seq, Wih, bih, Wio, bio);
    gru_rec<<<NCTA, NTHR, smem>>>(lens, Whh, bhh, Who, bho, out);
}